// round 17
// baseline (speedup 1.0000x reference)
#include <cuda_runtime.h>

// ============================================================================
// ROUND 17 — fused persistent FFMA2 kernel (interior + boundary in one grid),
// register-resident phase-1 constants, 2 barriers/tile.
// Verified I/O model: inputs dict-order element counts; output float32 concat
// [loss_pde, loss_bc, helm.real x N], out_size = 2 + N.
// ============================================================================

#define HID   128
#define N_INT 262144
#define N_BC  65536
#define PT    16
#define BPT   64
#define AP    129
#define NBLK  296
#define NT_I  (N_INT / PT)        // 16384
#define NT_B  (N_BC / BPT)        // 1024
#define NT_ALL (NT_I + NT_B)      // 17408

// smem float layout
#define S_W2  0
#define S_A   16384
#define S_B2  (16384 + 5 * PT * AP)    // 26704
#define S_W3  (S_B2 + 128)             // 26832
#define S_RED (S_W3 + 256)             // 27088
#define S_TOT (S_RED + 8)              // 27096 floats = 108384 bytes

__device__ float g_base1[HID];
__device__ float g_c1[HID];
__device__ float g_partial_pde[NBLK];
__device__ float g_partial_bc[NBLK];

__device__ __forceinline__ float tanh_acc(float x) {
    float ax = fabsf(x);
    float e  = __expf(-2.0f * ax);
    float r  = (1.0f - e) / (1.0f + e);
    return (x < 0.0f) ? -r : r;
}

__device__ __forceinline__ unsigned long long pack2(float lo, float hi) {
    unsigned long long r;
    asm("mov.b64 %0, {%1, %2};" : "=l"(r) : "f"(lo), "f"(hi));
    return r;
}
__device__ __forceinline__ void unpack2(unsigned long long v, float& lo, float& hi) {
    asm("mov.b64 {%0, %1}, %2;" : "=f"(lo), "=f"(hi) : "l"(v));
}
__device__ __forceinline__ void fma2(unsigned long long& d, unsigned long long a, unsigned long long b) {
    asm("fma.rn.f32x2 %0, %1, %2, %0;" : "+l"(d) : "l"(a), "l"(b));
}

// ---------------------------------------------------------------------------
__global__ void precompute_kernel(const float* __restrict__ latent,
                                  const float* __restrict__ W1,
                                  const float* __restrict__ b1) {
    int j = threadIdx.x;
    float b = b1[j];
    for (int i = 0; i < 64; ++i) b += latent[i] * W1[(3 + i) * HID + j];
    float c = 0.0f;
#pragma unroll
    for (int k = 0; k < 3; ++k) { float w = W1[k * HID + j]; c += w * w; }
    g_base1[j] = b;
    g_c1[j] = c;
}

// ---------------------------------------------------------------------------
// Fused persistent kernel: tiles [0, NT_I) interior-16, [NT_I, NT_ALL) bc-64.
// ---------------------------------------------------------------------------
__global__ __launch_bounds__(256, 2) void fused_kernel(
    const float* __restrict__ coordsI,
    const float* __restrict__ coordsB,
    const float* __restrict__ gt,
    const float* __restrict__ W1,
    const float* __restrict__ W2,
    const float* __restrict__ b2,
    const float* __restrict__ W3,
    const float* __restrict__ b3,
    float* __restrict__ outF, int helmMode, long long capF)
{
    extern __shared__ float smem[];
    float* W2s = smem + S_W2;
    float* A   = smem + S_A;
    float* b2s = smem + S_B2;
    float* W3s = smem + S_W3;
    float* red = smem + S_RED;

    const int tid  = threadIdx.x;
    const int g    = tid & 15;
    const int q    = tid >> 4;
    const int lane = tid & 31;
    const int rr   = tid >> 4;          // boundary row (same as q)

    // Per-j register constants (phase 1): j = tid & 127, ph = tid >> 7
    const int jr = tid & 127;
    const int ph = tid >> 7;            // point parity (p = ph + 2k)
    const float w0r = W1[jr], w1r = W1[HID + jr], w2r = W1[2 * HID + jr];
    const float base1r = g_base1[jr];
    const float c1r = g_c1[jr];

    for (int idx = tid; idx < HID * HID; idx += 256) W2s[idx] = W2[idx];
    if (tid < 128) b2s[tid] = b2[tid];
    if (tid < 256) W3s[tid] = W3[tid];
    const float b30 = b3[0], b31 = b3[1];

    float accPde = 0.0f, accBc = 0.0f;

    for (int tile = blockIdx.x; tile < NT_ALL; tile += gridDim.x) {
        __syncthreads();   // previous tile's GEMM consumed A

        if (tile < NT_I) {
            // ================= INTERIOR (16 points) =================
            const int p0 = tile * PT;

            // Phase 1: thread owns column jr; points p = ph + 2k (k=0..7)
#pragma unroll
            for (int k = 0; k < 8; ++k) {
                const int p  = ph + 2 * k;
                const int gp = p0 + p;
                float x0 = __ldg(&coordsI[3 * gp]);
                float x1 = __ldg(&coordsI[3 * gp + 1]);
                float x2 = __ldg(&coordsI[3 * gp + 2]);
                float z1 = base1r + x0 * w0r + x1 * w1r + x2 * w2r;
                float a1 = tanh_acc(z1);
                float t1 = 1.0f - a1 * a1;
                A[(0 * PT + p) * AP + jr] = a1;
                A[(1 * PT + p) * AP + jr] = t1 * w0r;
                A[(2 * PT + p) * AP + jr] = t1 * w1r;
                A[(3 * PT + p) * AP + jr] = t1 * w2r;
                A[(4 * PT + p) * AP + jr] = -2.0f * a1 * t1 * c1r;
            }
            __syncthreads();

            // Phase 2: 5-vector GEMM (FFMA2 register tile)
            unsigned long long acc[5][4];
#pragma unroll
            for (int m = 0; m < 5; ++m)
#pragma unroll
                for (int t = 0; t < 4; ++t) acc[m][t] = 0ULL;

            const float* Ap = A + q * AP;
            const float* Wp = W2s + 2 * g;
#pragma unroll 4
            for (int i = 0; i < HID; ++i) {
                float a0  = Ap[i];
                float a1v = Ap[PT * AP + i];
                float a2v = Ap[2 * PT * AP + i];
                float a3v = Ap[3 * PT * AP + i];
                float a4v = Ap[4 * PT * AP + i];
                unsigned long long d0 = pack2(a0,  a0);
                unsigned long long d1 = pack2(a1v, a1v);
                unsigned long long d2 = pack2(a2v, a2v);
                unsigned long long d3 = pack2(a3v, a3v);
                unsigned long long d4 = pack2(a4v, a4v);
                const float* wr = Wp + i * HID;
#pragma unroll
                for (int t = 0; t < 4; ++t) {
                    unsigned long long w = *(const unsigned long long*)(wr + 32 * t);
                    fma2(acc[0][t], d0, w);
                    fma2(acc[1][t], d1, w);
                    fma2(acc[2][t], d2, w);
                    fma2(acc[3][t], d3, w);
                    fma2(acc[4][t], d4, w);
                }
            }

            // Epilogue
            float yre = 0.f, yim = 0.f, lre = 0.f, lim = 0.f;
#pragma unroll
            for (int t = 0; t < 4; ++t) {
                float z2l, z2h, v0l, v0h, v1l, v1h, v2l, v2h, wl, wh;
                unpack2(acc[0][t], z2l, z2h);
                unpack2(acc[1][t], v0l, v0h);
                unpack2(acc[2][t], v1l, v1h);
                unpack2(acc[3][t], v2l, v2h);
                unpack2(acc[4][t], wl, wh);
                int j0 = 32 * t + 2 * g;
                {
                    float a2 = tanh_acc(z2l + b2s[j0]);
                    float t2 = 1.0f - a2 * a2;
                    float sv = v0l * v0l + v1l * v1l + v2l * v2l;
                    float e  = t2 * (wl - 2.0f * a2 * sv);
                    float w3r = W3s[2 * j0], w3i = W3s[2 * j0 + 1];
                    yre += a2 * w3r; yim += a2 * w3i;
                    lre += e * w3r;  lim += e * w3i;
                }
                {
                    int j1 = j0 + 1;
                    float a2 = tanh_acc(z2h + b2s[j1]);
                    float t2 = 1.0f - a2 * a2;
                    float sv = v0h * v0h + v1h * v1h + v2h * v2h;
                    float e  = t2 * (wh - 2.0f * a2 * sv);
                    float w3r = W3s[2 * j1], w3i = W3s[2 * j1 + 1];
                    yre += a2 * w3r; yim += a2 * w3i;
                    lre += e * w3r;  lim += e * w3i;
                }
            }
#pragma unroll
            for (int off = 8; off >= 1; off >>= 1) {
                yre += __shfl_xor_sync(0xffffffffu, yre, off);
                yim += __shfl_xor_sync(0xffffffffu, yim, off);
                lre += __shfl_xor_sync(0xffffffffu, lre, off);
                lim += __shfl_xor_sync(0xffffffffu, lim, off);
            }
            if (g == 0) {
                int gp = p0 + q;
                float pr = yre + b30, pi = yim + b31;
                float hr = lre + 4.0f * pr;   // K^2 = 4 (real)
                float hi = lim + 4.0f * pi;
                if (helmMode == 1) {
                    long long idx = 2LL + gp;
                    if (idx < capF) outF[idx] = hr;
                } else if (helmMode == 2) {
                    long long idx = 2LL + 2LL * gp;
                    if (idx + 1 < capF) { outF[idx] = hr; outF[idx + 1] = hi; }
                }
                accPde += hr * hr + hi * hi;
            }
        } else {
            // ================= BOUNDARY (64 points) =================
            const int p0 = (tile - NT_I) * BPT;

            // Phase 1: points p = ph + 2k (k=0..31)
#pragma unroll 8
            for (int k = 0; k < 32; ++k) {
                const int p  = ph + 2 * k;
                const int gp = p0 + p;
                float x0 = __ldg(&coordsB[3 * gp]);
                float x1 = __ldg(&coordsB[3 * gp + 1]);
                float x2 = __ldg(&coordsB[3 * gp + 2]);
                float z1 = base1r + x0 * w0r + x1 * w1r + x2 * w2r;
                A[p * AP + jr] = tanh_acc(z1);
            }
            __syncthreads();

            unsigned long long acc[4][4];
#pragma unroll
            for (int s = 0; s < 4; ++s)
#pragma unroll
                for (int t = 0; t < 4; ++t) acc[s][t] = 0ULL;

            const float* Wp = W2s + 2 * g;
#pragma unroll 4
            for (int i = 0; i < HID; ++i) {
                unsigned long long ds[4];
#pragma unroll
                for (int s = 0; s < 4; ++s) {
                    float a = A[(rr + 16 * s) * AP + i];
                    ds[s] = pack2(a, a);
                }
                const float* wr = Wp + i * HID;
#pragma unroll
                for (int t = 0; t < 4; ++t) {
                    unsigned long long w = *(const unsigned long long*)(wr + 32 * t);
                    fma2(acc[0][t], ds[0], w);
                    fma2(acc[1][t], ds[1], w);
                    fma2(acc[2][t], ds[2], w);
                    fma2(acc[3][t], ds[3], w);
                }
            }

#pragma unroll
            for (int s = 0; s < 4; ++s) {
                float yre = 0.f, yim = 0.f;
#pragma unroll
                for (int t = 0; t < 4; ++t) {
                    float zl, zh;
                    unpack2(acc[s][t], zl, zh);
                    int j0 = 32 * t + 2 * g;
                    float a2 = tanh_acc(zl + b2s[j0]);
                    yre += a2 * W3s[2 * j0]; yim += a2 * W3s[2 * j0 + 1];
                    int j1 = j0 + 1;
                    float a2b = tanh_acc(zh + b2s[j1]);
                    yre += a2b * W3s[2 * j1]; yim += a2b * W3s[2 * j1 + 1];
                }
#pragma unroll
                for (int off = 8; off >= 1; off >>= 1) {
                    yre += __shfl_xor_sync(0xffffffffu, yre, off);
                    yim += __shfl_xor_sync(0xffffffffu, yim, off);
                }
                if (g == 0) {
                    int gp = p0 + rr + 16 * s;
                    float dr = yre + b30 - __ldg(&gt[gp]);
                    float di = yim + b31;
                    accBc += dr * dr + di * di;
                }
            }
        }
    }

    // Block reductions (both losses)
#pragma unroll
    for (int off = 16; off >= 1; off >>= 1) {
        accPde += __shfl_xor_sync(0xffffffffu, accPde, off);
        accBc  += __shfl_xor_sync(0xffffffffu, accBc, off);
    }
    __syncthreads();
    if (lane == 0) red[tid >> 5] = accPde;
    __syncthreads();
    if (tid == 0) {
        float s = 0.f;
#pragma unroll
        for (int w = 0; w < 8; ++w) s += red[w];
        g_partial_pde[blockIdx.x] = s;
    }
    __syncthreads();
    if (lane == 0) red[tid >> 5] = accBc;
    __syncthreads();
    if (tid == 0) {
        float s = 0.f;
#pragma unroll
        for (int w = 0; w < 8; ++w) s += red[w];
        g_partial_bc[blockIdx.x] = s;
    }
}

// ---------------------------------------------------------------------------
__global__ void finalize_kernel(float* __restrict__ out, long long capF) {
    __shared__ float sp[256];
    __shared__ float sb[256];
    float a = 0.f, b = 0.f;
    for (int i = threadIdx.x; i < NBLK; i += 256) {
        a += g_partial_pde[i];
        b += g_partial_bc[i];
    }
    sp[threadIdx.x] = a; sb[threadIdx.x] = b;
    __syncthreads();
    for (int s = 128; s > 0; s >>= 1) {
        if (threadIdx.x < s) {
            sp[threadIdx.x] += sp[threadIdx.x + s];
            sb[threadIdx.x] += sb[threadIdx.x + s];
        }
        __syncthreads();
    }
    if (threadIdx.x == 0) {
        if (capF > 0) out[0] = sp[0] / (float)N_INT;
        if (capF > 1) out[1] = sb[0] / (float)N_BC;
    }
}

__global__ void sentinel_kernel(float* __restrict__ out, float v) {
    if (threadIdx.x == 0) out[0] = v;
}

// ---------------------------------------------------------------------------
extern "C" void kernel_launch(void* const* d_in, const int* in_sizes, int n_in,
                              void* d_out, int out_size) {
    static const long long dictE[10] = {786432, 196608, 65536, 64, 8576, 128,
                                        16384, 128, 256, 2};
    bool ok = (n_in >= 10);
    if (ok)
        for (int i = 0; i < 10; ++i)
            if ((long long)in_sizes[i] != dictE[i]) { ok = false; break; }

    float* out = (float*)d_out;
    if (!ok) { sentinel_kernel<<<1, 32>>>(out, 1e4f); return; }

    const float* CI = (const float*)d_in[0];
    const float* CB = (const float*)d_in[1];
    const float* GT = (const float*)d_in[2];
    const float* LA = (const float*)d_in[3];
    const float* W1 = (const float*)d_in[4];
    const float* B1 = (const float*)d_in[5];
    const float* W2 = (const float*)d_in[6];
    const float* B2 = (const float*)d_in[7];
    const float* W3 = (const float*)d_in[8];
    const float* B3 = (const float*)d_in[9];

    const long long N = N_INT, os = out_size;
    int helmMode;
    if      (os == 2 + N)      helmMode = 1;   // verified model
    else if (os >= 2 + 2 * N)  helmMode = 2;
    else                       helmMode = 0;
    const long long capF = os;

    const size_t SH = S_TOT * sizeof(float);   // 108384 bytes
    cudaFuncSetAttribute(fused_kernel, cudaFuncAttributeMaxDynamicSharedMemorySize, (int)SH);

    precompute_kernel<<<1, HID>>>(LA, W1, B1);
    fused_kernel<<<NBLK, 256, SH>>>(CI, CB, GT, W1, W2, B2, W3, B3,
                                    out, helmMode, capF);
    finalize_kernel<<<1, 256>>>(out, capF);
}